// round 5
// baseline (speedup 1.0000x reference)
#include <cuda_runtime.h>
#include <cstdint>
#include <math.h>

// Problem constants (fixed shapes)
#define N_BATCH 64
#define DIM     512   // d (contraction for QK)
#define CQ      512   // c (query positions)
#define TT      1024  // t = h*w
#define WW      128   // w
#define SCALE   0.04419417382415922f  // 512^-0.5

// 128 MB scratch for logits/weights [n][c][t]
static __device__ float g_logits[(size_t)N_BATCH * CQ * TT];

// ---------------------------------------------------------------------------
// helpers
// ---------------------------------------------------------------------------
__device__ __forceinline__ float tf32rf(float x) {
    unsigned u;
    asm("cvt.rna.tf32.f32 %0, %1;" : "=r"(u) : "f"(x));
    return __uint_as_float(u);
}

__device__ __forceinline__ void mma_tf32(float c[4],
                                         uint32_t a0, uint32_t a1, uint32_t a2, uint32_t a3,
                                         uint32_t b0, uint32_t b1) {
    asm volatile(
        "mma.sync.aligned.m16n8k8.row.col.f32.tf32.tf32.f32 "
        "{%0,%1,%2,%3}, {%4,%5,%6,%7}, {%8,%9}, {%0,%1,%2,%3};"
        : "+f"(c[0]), "+f"(c[1]), "+f"(c[2]), "+f"(c[3])
        : "r"(a0), "r"(a1), "r"(a2), "r"(a3), "r"(b0), "r"(b1));
}

// ---------------------------------------------------------------------------
// GEMM1 (TN): L[n][c][t] = SCALE * sum_d Q[n][d][c] * K[n][d][t]
// Natural [k][x] global layout -> smem [k][m]/[k][n], no transpose needed.
// CTA tile 256(c) x 128(t), 8 warps as 4(m) x 2(n), warp tile 64x64.
// KC=16. Pitches 264/136 (mod 32 == 8) -> conflict-free fragment LDS.
// ---------------------------------------------------------------------------
__global__ __launch_bounds__(256, 1) void gemm_qk(
    const float* __restrict__ Q, const float* __restrict__ Kp,
    float* __restrict__ L)
{
    __shared__ float As[16][264];
    __shared__ float Bs[16][136];

    const int n  = blockIdx.z;
    const float* Qb = Q  + (size_t)n * DIM * CQ;
    const float* Kb = Kp + (size_t)n * DIM * TT;
    float*       Lb = L  + (size_t)n * CQ  * TT;
    const int c0 = blockIdx.y * 256;
    const int t0 = blockIdx.x * 128;

    const int tid  = threadIdx.x;
    const int wid  = tid >> 5;
    const int lane = tid & 31;
    const int g    = lane >> 2;
    const int tig  = lane & 3;
    const int mOff = (wid >> 1) * 64;   // 0,64,128,192
    const int nOff = (wid & 1) * 64;    // 0,64

    // loader: row = tid/16 (0..15), col base = (tid%16)*4
    const int lrow = tid >> 4;
    const int lcol = (tid & 15) << 2;

    float acc[4][8][4];
    #pragma unroll
    for (int i = 0; i < 4; i++)
        #pragma unroll
        for (int j = 0; j < 8; j++)
            #pragma unroll
            for (int r = 0; r < 4; r++) acc[i][j][r] = 0.f;

    const float* qp = Qb + (size_t)lrow * CQ + c0 + lcol;
    const float* kp = Kb + (size_t)lrow * TT + t0 + lcol;

    float4 ar[4], br[2];
    #pragma unroll
    for (int j = 0; j < 4; j++) ar[j] = *(const float4*)(qp + 64 * j);
    #pragma unroll
    for (int j = 0; j < 2; j++) br[j] = *(const float4*)(kp + 64 * j);

    for (int c = 0; c < DIM / 16; c++) {
        __syncthreads();
        #pragma unroll
        for (int j = 0; j < 4; j++) {
            float* s = &As[lrow][lcol + 64 * j];
            s[0] = tf32rf(ar[j].x); s[1] = tf32rf(ar[j].y);
            s[2] = tf32rf(ar[j].z); s[3] = tf32rf(ar[j].w);
        }
        #pragma unroll
        for (int j = 0; j < 2; j++) {
            float* s = &Bs[lrow][lcol + 64 * j];
            s[0] = tf32rf(br[j].x); s[1] = tf32rf(br[j].y);
            s[2] = tf32rf(br[j].z); s[3] = tf32rf(br[j].w);
        }
        __syncthreads();

        if (c + 1 < DIM / 16) {
            qp += 16 * CQ;
            kp += 16 * TT;
            #pragma unroll
            for (int j = 0; j < 4; j++) ar[j] = *(const float4*)(qp + 64 * j);
            #pragma unroll
            for (int j = 0; j < 2; j++) br[j] = *(const float4*)(kp + 64 * j);
        }

        #pragma unroll
        for (int ks = 0; ks < 2; ks++) {
            const int kk = ks * 8;
            uint32_t a[4][4];
            #pragma unroll
            for (int i = 0; i < 4; i++) {
                const int mb = mOff + 16 * i;
                a[i][0] = __float_as_uint(As[kk + tig    ][mb + g    ]);
                a[i][1] = __float_as_uint(As[kk + tig    ][mb + g + 8]);
                a[i][2] = __float_as_uint(As[kk + tig + 4][mb + g    ]);
                a[i][3] = __float_as_uint(As[kk + tig + 4][mb + g + 8]);
            }
            uint32_t b[8][2];
            #pragma unroll
            for (int j = 0; j < 8; j++) {
                const int nb = nOff + 8 * j + g;
                b[j][0] = __float_as_uint(Bs[kk + tig    ][nb]);
                b[j][1] = __float_as_uint(Bs[kk + tig + 4][nb]);
            }
            #pragma unroll
            for (int i = 0; i < 4; i++)
                #pragma unroll
                for (int j = 0; j < 8; j++)
                    mma_tf32(acc[i][j], a[i][0], a[i][1], a[i][2], a[i][3],
                             b[j][0], b[j][1]);
        }
    }

    #pragma unroll
    for (int i = 0; i < 4; i++) {
        const int row0 = c0 + mOff + 16 * i + g;
        #pragma unroll
        for (int j = 0; j < 8; j++) {
            const int colb = t0 + nOff + 8 * j + 2 * tig;
            *(float2*)(Lb + (size_t)row0 * TT + colb) =
                make_float2(acc[i][j][0] * SCALE, acc[i][j][1] * SCALE);
            *(float2*)(Lb + (size_t)(row0 + 8) * TT + colb) =
                make_float2(acc[i][j][2] * SCALE, acc[i][j][3] * SCALE);
        }
    }
}

// ---------------------------------------------------------------------------
// Fused mask + softmax over t (in place), emits tf32-rounded weights.
// Mask: (t % 128) < vw[n], vw = min(128, floor(128*ratio + 0.5)).
// ---------------------------------------------------------------------------
__global__ __launch_bounds__(256) void softmax_mask_kernel(
    float* __restrict__ L, const float* __restrict__ ratios)
{
    const int row = blockIdx.x;
    const int n   = row >> 9;
    float* p = L + (size_t)row * TT;

    const float ratio = ratios[n];
    int vw = (int)floorf((float)WW * ratio + 0.5f);
    vw = vw > WW ? WW : vw;

    const int tid  = threadIdx.x;
    const int base = tid << 2;
    float4 v = ((const float4*)p)[tid];
    float vals[4] = {v.x, v.y, v.z, v.w};
    #pragma unroll
    for (int i = 0; i < 4; i++) {
        int wi = (base + i) & (WW - 1);
        if (wi >= vw) vals[i] = -INFINITY;
    }

    __shared__ float red_max[8];
    __shared__ float red_sum[8];
    const int lane = tid & 31;
    const int warp = tid >> 5;

    float m = fmaxf(fmaxf(vals[0], vals[1]), fmaxf(vals[2], vals[3]));
    #pragma unroll
    for (int off = 16; off > 0; off >>= 1)
        m = fmaxf(m, __shfl_xor_sync(0xffffffffu, m, off));
    if (lane == 0) red_max[warp] = m;
    __syncthreads();
    float mall = red_max[0];
    #pragma unroll
    for (int i = 1; i < 8; i++) mall = fmaxf(mall, red_max[i]);

    float s = 0.f;
    #pragma unroll
    for (int i = 0; i < 4; i++) {
        vals[i] = expf(vals[i] - mall);
        s += vals[i];
    }
    #pragma unroll
    for (int off = 16; off > 0; off >>= 1)
        s += __shfl_xor_sync(0xffffffffu, s, off);
    if (lane == 0) red_sum[warp] = s;
    __syncthreads();
    float sall = 0.f;
    #pragma unroll
    for (int i = 0; i < 8; i++) sall += red_sum[i];

    const float inv = 1.0f / sall;
    ((float4*)p)[tid] = make_float4(tf32rf(vals[0] * inv), tf32rf(vals[1] * inv),
                                    tf32rf(vals[2] * inv), tf32rf(vals[3] * inv));
}

// ---------------------------------------------------------------------------
// GEMM2 (NT): O[n][d][c] = sum_t V[n][d][t] * W[n][c][t]
// t contiguous for both -> smem [m][k]/[n][k], pitch 20 (conflict-free).
// CTA tile 256(d) x 128(c), 8 warps as 4x2, warp tile 64x64, KC=16.
// V rounded to tf32 in the loader; W already rounded by softmax.
// ---------------------------------------------------------------------------
__global__ __launch_bounds__(256, 1) void gemm_wv(
    const float* __restrict__ V, const float* __restrict__ W,
    float* __restrict__ O)
{
    __shared__ float As[256][20];
    __shared__ float Bs[128][20];

    const int n  = blockIdx.z;
    const float* Vb = V + (size_t)n * DIM * TT;
    const float* Wb = W + (size_t)n * CQ  * TT;
    float*       Ob = O + (size_t)n * DIM * CQ;
    const int d0 = blockIdx.y * 256;
    const int c0 = blockIdx.x * 128;

    const int tid  = threadIdx.x;
    const int wid  = tid >> 5;
    const int lane = tid & 31;
    const int g    = lane >> 2;
    const int tig  = lane & 3;
    const int mOff = (wid >> 1) * 64;
    const int nOff = (wid & 1) * 64;

    // A loader: one row per thread, 16 consecutive floats (4x float4)
    const float* vp = Vb + (size_t)(d0 + tid) * TT;
    // B loader: 2 threads per row, 8 floats each as 2x float4 at h*4 + 8*j
    const int brow = tid >> 1;
    const int bh   = (tid & 1) << 2;   // 0 or 4
    const float* wp = Wb + (size_t)(c0 + brow) * TT + bh;

    float acc[4][8][4];
    #pragma unroll
    for (int i = 0; i < 4; i++)
        #pragma unroll
        for (int j = 0; j < 8; j++)
            #pragma unroll
            for (int r = 0; r < 4; r++) acc[i][j][r] = 0.f;

    float4 ar[4], br[2];
    #pragma unroll
    for (int j = 0; j < 4; j++) ar[j] = *(const float4*)(vp + 4 * j);
    #pragma unroll
    for (int j = 0; j < 2; j++) br[j] = *(const float4*)(wp + 8 * j);

    for (int c = 0; c < TT / 16; c++) {
        __syncthreads();
        #pragma unroll
        for (int j = 0; j < 4; j++) {
            float* s = &As[tid][4 * j];
            s[0] = tf32rf(ar[j].x); s[1] = tf32rf(ar[j].y);
            s[2] = tf32rf(ar[j].z); s[3] = tf32rf(ar[j].w);
        }
        #pragma unroll
        for (int j = 0; j < 2; j++) {
            *(float4*)(&Bs[brow][bh + 8 * j]) = br[j];  // already tf32
        }
        __syncthreads();

        if (c + 1 < TT / 16) {
            vp += 16;
            wp += 16;
            #pragma unroll
            for (int j = 0; j < 4; j++) ar[j] = *(const float4*)(vp + 4 * j);
            #pragma unroll
            for (int j = 0; j < 2; j++) br[j] = *(const float4*)(wp + 8 * j);
        }

        #pragma unroll
        for (int ks = 0; ks < 2; ks++) {
            const int kk = ks * 8;
            uint32_t a[4][4];
            #pragma unroll
            for (int i = 0; i < 4; i++) {
                const int mb = mOff + 16 * i;
                a[i][0] = __float_as_uint(As[mb + g    ][kk + tig    ]);
                a[i][1] = __float_as_uint(As[mb + g + 8][kk + tig    ]);
                a[i][2] = __float_as_uint(As[mb + g    ][kk + tig + 4]);
                a[i][3] = __float_as_uint(As[mb + g + 8][kk + tig + 4]);
            }
            uint32_t b[8][2];
            #pragma unroll
            for (int j = 0; j < 8; j++) {
                const int nb = nOff + 8 * j + g;
                b[j][0] = __float_as_uint(Bs[nb][kk + tig    ]);
                b[j][1] = __float_as_uint(Bs[nb][kk + tig + 4]);
            }
            #pragma unroll
            for (int i = 0; i < 4; i++)
                #pragma unroll
                for (int j = 0; j < 8; j++)
                    mma_tf32(acc[i][j], a[i][0], a[i][1], a[i][2], a[i][3],
                             b[j][0], b[j][1]);
        }
    }

    #pragma unroll
    for (int i = 0; i < 4; i++) {
        const int row0 = d0 + mOff + 16 * i + g;
        #pragma unroll
        for (int j = 0; j < 8; j++) {
            const int colb = c0 + nOff + 8 * j + 2 * tig;
            *(float2*)(Ob + (size_t)row0 * CQ + colb) =
                make_float2(acc[i][j][0], acc[i][j][1]);
            *(float2*)(Ob + (size_t)(row0 + 8) * CQ + colb) =
                make_float2(acc[i][j][2], acc[i][j][3]);
        }
    }
}

// ---------------------------------------------------------------------------
extern "C" void kernel_launch(void* const* d_in, const int* in_sizes, int n_in,
                              void* d_out, int out_size)
{
    const float* query  = (const float*)d_in[0];  // [64, 512, 512]
    const float* key    = (const float*)d_in[1];  // [64, 512, 1024]
    const float* value  = (const float*)d_in[2];  // [64, 512, 1024]
    const float* ratios = (const float*)d_in[3];  // [64]
    float* out = (float*)d_out;                   // [64, 512, 512]

    float* logits = nullptr;
    cudaGetSymbolAddress((void**)&logits, g_logits);

    // 1) logits = Q^T K * SCALE  (CTA 256c x 128t)
    {
        dim3 grid(TT / 128, CQ / 256, N_BATCH);  // (8, 2, 64)
        gemm_qk<<<grid, 256>>>(query, key, logits);
    }
    // 2) mask + softmax (in place, tf32-rounded weights)
    softmax_mask_kernel<<<N_BATCH * CQ, 256>>>(logits, ratios);
    // 3) out = V x W^T  (CTA 256d x 128c)
    {
        dim3 grid(CQ / 128, DIM / 256, N_BATCH);  // (4, 2, 64)
        gemm_wv<<<grid, 256>>>(value, logits, out);
    }
}

// round 7
// speedup vs baseline: 1.4575x; 1.4575x over previous
#include <cuda_runtime.h>
#include <cuda_fp16.h>
#include <cstdint>
#include <math.h>

#define N_BATCH 64
#define DIM     512
#define CQ      512
#define TT      1024
#define WW      128
#define SCALE   0.04419417382415922f  // 512^-0.5

static __device__ float  g_logits[(size_t)N_BATCH * CQ * TT];  // 128 MB
static __device__ __half g_wh[(size_t)N_BATCH * CQ * TT];      // 64 MB half weights

// ---------------------------------------------------------------------------
__device__ __forceinline__ uint32_t f22h(float x, float y) {
    __half2 h = __floats2half2_rn(x, y);
    return *(uint32_t*)&h;
}

__device__ __forceinline__ void mma_f16(float c[4],
                                        uint32_t a0, uint32_t a1, uint32_t a2, uint32_t a3,
                                        uint32_t b0, uint32_t b1) {
    asm volatile(
        "mma.sync.aligned.m16n8k16.row.col.f32.f16.f16.f32 "
        "{%0,%1,%2,%3}, {%4,%5,%6,%7}, {%8,%9}, {%0,%1,%2,%3};"
        : "+f"(c[0]), "+f"(c[1]), "+f"(c[2]), "+f"(c[3])
        : "r"(a0), "r"(a1), "r"(a2), "r"(a3), "r"(b0), "r"(b1));
}

// ---------------------------------------------------------------------------
// GEMM1 (TN): L[n][c][t] = sum_d (Q[n][d][c]*SCALE) * K[n][d][t]
// fp16 mma m16n8k16. smem [kpair][x] of uint32 (half2 = 2 consecutive k).
// CTA 256(c) x 128(t), 8 warps 4x2, warp tile 64x64, KC = 32 k (16 pairs).
// Pitches 264/136 (mod 32 == 8) -> conflict-free fragment LDS (R5-proven).
// ---------------------------------------------------------------------------
__global__ __launch_bounds__(256, 1) void gemm_qk(
    const float* __restrict__ Q, const float* __restrict__ Kp,
    float* __restrict__ L)
{
    __shared__ uint32_t As[16][264];   // [kpair][c]
    __shared__ uint32_t Bs[16][136];   // [kpair][t]

    const int n  = blockIdx.z;
    const float* Qb = Q  + (size_t)n * DIM * CQ;
    const float* Kb = Kp + (size_t)n * DIM * TT;
    float*       Lb = L  + (size_t)n * CQ  * TT;
    const int c0 = blockIdx.y * 256;
    const int t0 = blockIdx.x * 128;

    const int tid  = threadIdx.x;
    const int wid  = tid >> 5;
    const int lane = tid & 31;
    const int g    = lane >> 2;
    const int tig  = lane & 3;
    const int mOff = (wid >> 1) * 64;
    const int nOff = (wid & 1) * 64;

    // loaders: pair-row = tid>>4 (0..15), A cols 16/thread, B cols 8/thread
    const int prow  = tid >> 4;
    const int lcolA = (tid & 15) << 4;
    const int lcolB = (tid & 15) << 3;

    const float* qp0 = Qb + (size_t)(2 * prow)     * CQ + c0 + lcolA;
    const float* qp1 = Qb + (size_t)(2 * prow + 1) * CQ + c0 + lcolA;
    const float* kp0 = Kb + (size_t)(2 * prow)     * TT + t0 + lcolB;
    const float* kp1 = Kb + (size_t)(2 * prow + 1) * TT + t0 + lcolB;

    float acc[4][8][4];
    #pragma unroll
    for (int i = 0; i < 4; i++)
        #pragma unroll
        for (int j = 0; j < 8; j++)
            #pragma unroll
            for (int r = 0; r < 4; r++) acc[i][j][r] = 0.f;

    float4 a0r[4], a1r[4], b0r[2], b1r[2];
    #pragma unroll
    for (int j = 0; j < 4; j++) {
        a0r[j] = *(const float4*)(qp0 + 4 * j);
        a1r[j] = *(const float4*)(qp1 + 4 * j);
    }
    #pragma unroll
    for (int j = 0; j < 2; j++) {
        b0r[j] = *(const float4*)(kp0 + 4 * j);
        b1r[j] = *(const float4*)(kp1 + 4 * j);
    }

    for (int c = 0; c < DIM / 32; c++) {
        __syncthreads();
        #pragma unroll
        for (int j = 0; j < 4; j++) {
            uint32_t* s = &As[prow][lcolA + 4 * j];
            s[0] = f22h(a0r[j].x * SCALE, a1r[j].x * SCALE);
            s[1] = f22h(a0r[j].y * SCALE, a1r[j].y * SCALE);
            s[2] = f22h(a0r[j].z * SCALE, a1r[j].z * SCALE);
            s[3] = f22h(a0r[j].w * SCALE, a1r[j].w * SCALE);
        }
        #pragma unroll
        for (int j = 0; j < 2; j++) {
            uint32_t* s = &Bs[prow][lcolB + 4 * j];
            s[0] = f22h(b0r[j].x, b1r[j].x);
            s[1] = f22h(b0r[j].y, b1r[j].y);
            s[2] = f22h(b0r[j].z, b1r[j].z);
            s[3] = f22h(b0r[j].w, b1r[j].w);
        }
        __syncthreads();

        if (c + 1 < DIM / 32) {
            qp0 += 32 * CQ; qp1 += 32 * CQ;
            kp0 += 32 * TT; kp1 += 32 * TT;
            #pragma unroll
            for (int j = 0; j < 4; j++) {
                a0r[j] = *(const float4*)(qp0 + 4 * j);
                a1r[j] = *(const float4*)(qp1 + 4 * j);
            }
            #pragma unroll
            for (int j = 0; j < 2; j++) {
                b0r[j] = *(const float4*)(kp0 + 4 * j);
                b1r[j] = *(const float4*)(kp1 + 4 * j);
            }
        }

        #pragma unroll
        for (int ks = 0; ks < 2; ks++) {
            const int kk = ks * 8;   // pair index base of this k16 step
            uint32_t a[4][4];
            #pragma unroll
            for (int i = 0; i < 4; i++) {
                const int mb = mOff + 16 * i;
                a[i][0] = As[kk + tig    ][mb + g    ];
                a[i][1] = As[kk + tig    ][mb + g + 8];
                a[i][2] = As[kk + tig + 4][mb + g    ];
                a[i][3] = As[kk + tig + 4][mb + g + 8];
            }
            uint32_t b[8][2];
            #pragma unroll
            for (int j = 0; j < 8; j++) {
                const int nb = nOff + 8 * j + g;
                b[j][0] = Bs[kk + tig    ][nb];
                b[j][1] = Bs[kk + tig + 4][nb];
            }
            #pragma unroll
            for (int i = 0; i < 4; i++)
                #pragma unroll
                for (int j = 0; j < 8; j++)
                    mma_f16(acc[i][j], a[i][0], a[i][1], a[i][2], a[i][3],
                            b[j][0], b[j][1]);
        }
    }

    #pragma unroll
    for (int i = 0; i < 4; i++) {
        const int row0 = c0 + mOff + 16 * i + g;
        #pragma unroll
        for (int j = 0; j < 8; j++) {
            const int colb = t0 + nOff + 8 * j + 2 * tig;
            *(float2*)(Lb + (size_t)row0 * TT + colb) =
                make_float2(acc[i][j][0], acc[i][j][1]);
            *(float2*)(Lb + (size_t)(row0 + 8) * TT + colb) =
                make_float2(acc[i][j][2], acc[i][j][3]);
        }
    }
}

// ---------------------------------------------------------------------------
// Fused mask + softmax over t; fp32 logits in, HALF weights out.
// Mask: (t % 128) < vw[n], vw = min(128, floor(128*ratio + 0.5)).
// ---------------------------------------------------------------------------
__global__ __launch_bounds__(256) void softmax_mask_kernel(
    const float* __restrict__ L, __half* __restrict__ Wh,
    const float* __restrict__ ratios)
{
    const int row = blockIdx.x;
    const int n   = row >> 9;
    const float* p = L + (size_t)row * TT;

    const float ratio = ratios[n];
    int vw = (int)floorf((float)WW * ratio + 0.5f);
    vw = vw > WW ? WW : vw;

    const int tid  = threadIdx.x;
    const int base = tid << 2;
    float4 v = ((const float4*)p)[tid];
    float vals[4] = {v.x, v.y, v.z, v.w};
    #pragma unroll
    for (int i = 0; i < 4; i++) {
        int wi = (base + i) & (WW - 1);
        if (wi >= vw) vals[i] = -INFINITY;
    }

    __shared__ float red_max[8];
    __shared__ float red_sum[8];
    const int lane = tid & 31;
    const int warp = tid >> 5;

    float m = fmaxf(fmaxf(vals[0], vals[1]), fmaxf(vals[2], vals[3]));
    #pragma unroll
    for (int off = 16; off > 0; off >>= 1)
        m = fmaxf(m, __shfl_xor_sync(0xffffffffu, m, off));
    if (lane == 0) red_max[warp] = m;
    __syncthreads();
    float mall = red_max[0];
    #pragma unroll
    for (int i = 1; i < 8; i++) mall = fmaxf(mall, red_max[i]);

    float s = 0.f;
    #pragma unroll
    for (int i = 0; i < 4; i++) {
        vals[i] = expf(vals[i] - mall);
        s += vals[i];
    }
    #pragma unroll
    for (int off = 16; off > 0; off >>= 1)
        s += __shfl_xor_sync(0xffffffffu, s, off);
    if (lane == 0) red_sum[warp] = s;
    __syncthreads();
    float sall = 0.f;
    #pragma unroll
    for (int i = 0; i < 8; i++) sall += red_sum[i];

    const float inv = 1.0f / sall;
    uint2 o;
    o.x = f22h(vals[0] * inv, vals[1] * inv);
    o.y = f22h(vals[2] * inv, vals[3] * inv);
    ((uint2*)(Wh + (size_t)row * TT))[tid] = o;
}

// ---------------------------------------------------------------------------
// GEMM2 (NT): O[n][d][c] = sum_t V[n][d][t] * W[n][c][t]
// fp16 mma. smem [x][kpair] of uint32, pitch 20 (R5-proven conflict-free).
// CTA 256(d) x 128(c), warps 4x2 of 64x64, KC = 32 t (16 pairs).
// V converted in loader (pairs = consecutive t); W already half in gmem.
// ---------------------------------------------------------------------------
__global__ __launch_bounds__(256, 1) void gemm_wv(
    const float* __restrict__ V, const __half* __restrict__ W,
    float* __restrict__ O)
{
    __shared__ uint32_t As[256][20];   // [d][kpair]
    __shared__ uint32_t Bs[128][20];   // [c][kpair]

    const int n  = blockIdx.z;
    const float*  Vb = V + (size_t)n * DIM * TT;
    const __half* Wb = W + (size_t)n * CQ  * TT;
    float*        Ob = O + (size_t)n * DIM * CQ;
    const int d0 = blockIdx.y * 256;
    const int c0 = blockIdx.x * 128;

    const int tid  = threadIdx.x;
    const int wid  = tid >> 5;
    const int lane = tid & 31;
    const int g    = lane >> 2;
    const int tig  = lane & 3;
    const int mOff = (wid >> 1) * 64;
    const int nOff = (wid & 1) * 64;

    // A loader: one d-row per thread, 32 t (8 float4) -> 16 pairs
    const float* vp = Vb + (size_t)(d0 + tid) * TT;
    // B loader: 2 threads per c-row, 8 uint32 (2 uint4) each
    const int brow = tid >> 1;
    const int bseg = tid & 1;
    const uint4* wp = (const uint4*)(Wb + (size_t)(c0 + brow) * TT) + 2 * bseg;

    float acc[4][8][4];
    #pragma unroll
    for (int i = 0; i < 4; i++)
        #pragma unroll
        for (int j = 0; j < 8; j++)
            #pragma unroll
            for (int r = 0; r < 4; r++) acc[i][j][r] = 0.f;

    float4 vR[8];
    uint4  wR[2];
    #pragma unroll
    for (int s = 0; s < 8; s++) vR[s] = *(const float4*)(vp + 4 * s);
    wR[0] = wp[0];
    wR[1] = wp[1];

    for (int c = 0; c < TT / 32; c++) {
        __syncthreads();
        #pragma unroll
        for (int s = 0; s < 4; s++) {
            uint4 u;
            u.x = f22h(vR[2*s].x,   vR[2*s].y);
            u.y = f22h(vR[2*s].z,   vR[2*s].w);
            u.z = f22h(vR[2*s+1].x, vR[2*s+1].y);
            u.w = f22h(vR[2*s+1].z, vR[2*s+1].w);
            *(uint4*)(&As[tid][4 * s]) = u;
        }
        *(uint4*)(&Bs[brow][8 * bseg])     = wR[0];
        *(uint4*)(&Bs[brow][8 * bseg + 4]) = wR[1];
        __syncthreads();

        if (c + 1 < TT / 32) {
            vp += 32;
            #pragma unroll
            for (int s = 0; s < 8; s++) vR[s] = *(const float4*)(vp + 4 * s);
            wR[0] = wp[4 * (c + 1)];
            wR[1] = wp[4 * (c + 1) + 1];
        }

        #pragma unroll
        for (int ks = 0; ks < 2; ks++) {
            const int kk = ks * 8;
            uint32_t a[4][4];
            #pragma unroll
            for (int i = 0; i < 4; i++) {
                const int mb = mOff + 16 * i;
                a[i][0] = As[mb + g    ][kk + tig    ];
                a[i][1] = As[mb + g + 8][kk + tig    ];
                a[i][2] = As[mb + g    ][kk + tig + 4];
                a[i][3] = As[mb + g + 8][kk + tig + 4];
            }
            uint32_t b[8][2];
            #pragma unroll
            for (int j = 0; j < 8; j++) {
                const int nb = nOff + 8 * j + g;
                b[j][0] = Bs[nb][kk + tig    ];
                b[j][1] = Bs[nb][kk + tig + 4];
            }
            #pragma unroll
            for (int i = 0; i < 4; i++)
                #pragma unroll
                for (int j = 0; j < 8; j++)
                    mma_f16(acc[i][j], a[i][0], a[i][1], a[i][2], a[i][3],
                            b[j][0], b[j][1]);
        }
    }

    #pragma unroll
    for (int i = 0; i < 4; i++) {
        const int row0 = d0 + mOff + 16 * i + g;
        #pragma unroll
        for (int j = 0; j < 8; j++) {
            const int colb = c0 + nOff + 8 * j + 2 * tig;
            *(float2*)(Ob + (size_t)row0 * CQ + colb) =
                make_float2(acc[i][j][0], acc[i][j][1]);
            *(float2*)(Ob + (size_t)(row0 + 8) * CQ + colb) =
                make_float2(acc[i][j][2], acc[i][j][3]);
        }
    }
}

// ---------------------------------------------------------------------------
extern "C" void kernel_launch(void* const* d_in, const int* in_sizes, int n_in,
                              void* d_out, int out_size)
{
    const float* query  = (const float*)d_in[0];  // [64, 512, 512]
    const float* key    = (const float*)d_in[1];  // [64, 512, 1024]
    const float* value  = (const float*)d_in[2];  // [64, 512, 1024]
    const float* ratios = (const float*)d_in[3];  // [64]
    float* out = (float*)d_out;                   // [64, 512, 512]

    float*  logits = nullptr;
    __half* wh     = nullptr;
    cudaGetSymbolAddress((void**)&logits, g_logits);
    cudaGetSymbolAddress((void**)&wh, g_wh);

    // 1) logits = (Q*SCALE)^T K   (fp16 tensor cores)
    {
        dim3 grid(TT / 128, CQ / 256, N_BATCH);  // (8, 2, 64)
        gemm_qk<<<grid, 256>>>(query, key, logits);
    }
    // 2) mask + softmax -> half weights
    softmax_mask_kernel<<<N_BATCH * CQ, 256>>>(logits, wh, ratios);
    // 3) out = V x W^T   (fp16 tensor cores)
    {
        dim3 grid(CQ / 128, DIM / 256, N_BATCH);  // (4, 2, 64)
        gemm_wv<<<grid, 256>>>(value, wh, out);
    }
}

// round 8
// speedup vs baseline: 1.6488x; 1.1312x over previous
#include <cuda_runtime.h>
#include <cuda_fp16.h>
#include <cstdint>
#include <math.h>

#define N_BATCH 64
#define DIM     512
#define CQ      512
#define TT      1024
#define WW      128
#define SCALE   0.04419417382415922f  // 512^-0.5

// Scratch (device globals)
static __device__ float    g_logits[(size_t)N_BATCH * CQ * TT];        // 128 MB
static __device__ __half   g_wh[(size_t)N_BATCH * CQ * TT];            // 64 MB weights (half)
static __device__ uint32_t g_qh[(size_t)N_BATCH * (DIM/2) * CQ];       // 32 MB Q pair-interleaved half2
static __device__ uint32_t g_kh[(size_t)N_BATCH * (DIM/2) * TT];       // 64 MB K pair-interleaved half2
static __device__ uint32_t g_vh[(size_t)N_BATCH * DIM * (TT/2)];       // 64 MB V half (t-pairs)

// ---------------------------------------------------------------------------
__device__ __forceinline__ uint32_t smem_u32(const void* p) {
    uint32_t a;
    asm("{ .reg .u64 t; cvta.to.shared.u64 t, %1; cvt.u32.u64 %0, t; }"
        : "=r"(a) : "l"(p));
    return a;
}

__device__ __forceinline__ uint32_t f22h(float x, float y) {
    __half2 h = __floats2half2_rn(x, y);
    return *(uint32_t*)&h;
}

__device__ __forceinline__ void mma_f16(float c[4],
                                        uint32_t a0, uint32_t a1, uint32_t a2, uint32_t a3,
                                        uint32_t b0, uint32_t b1) {
    asm volatile(
        "mma.sync.aligned.m16n8k16.row.col.f32.f16.f16.f32 "
        "{%0,%1,%2,%3}, {%4,%5,%6,%7}, {%8,%9}, {%0,%1,%2,%3};"
        : "+f"(c[0]), "+f"(c[1]), "+f"(c[2]), "+f"(c[3])
        : "r"(a0), "r"(a1), "r"(a2), "r"(a3), "r"(b0), "r"(b1));
}

__device__ __forceinline__ void cp16(uint32_t saddr, const void* gaddr) {
    asm volatile("cp.async.cg.shared.global [%0], [%1], 16;"
        :: "r"(saddr), "l"(gaddr) : "memory");
}

// ---------------------------------------------------------------------------
// Conversion passes
// ---------------------------------------------------------------------------
// out[n][p][x] = half2(in[n][2p][x], in[n][2p+1][x]) * mul ; 128 threads/blk
__global__ __launch_bounds__(128) void pairify(
    const float* __restrict__ in, uint32_t* __restrict__ out,
    int W, float mul)
{
    const int n   = blockIdx.z;
    const int p   = blockIdx.y;
    const int P   = gridDim.y;        // DIM/2
    const int col = (blockIdx.x * 128 + threadIdx.x) * 4;

    const float* r0 = in + ((size_t)n * 2 * P + 2 * p) * W + col;
    const float* r1 = r0 + W;
    float4 a = *(const float4*)r0;
    float4 b = *(const float4*)r1;
    uint4 o;
    o.x = f22h(a.x * mul, b.x * mul);
    o.y = f22h(a.y * mul, b.y * mul);
    o.z = f22h(a.z * mul, b.z * mul);
    o.w = f22h(a.w * mul, b.w * mul);
    *(uint4*)(out + ((size_t)n * P + p) * W + col) = o;
}

// elementwise fp32 -> half, 8 floats per thread
__global__ __launch_bounds__(256) void vconv(
    const float4* __restrict__ in, uint4* __restrict__ out)
{
    const size_t i = (size_t)blockIdx.x * 256 + threadIdx.x;
    float4 a = in[2 * i];
    float4 b = in[2 * i + 1];
    uint4 o;
    o.x = f22h(a.x, a.y);
    o.y = f22h(a.z, a.w);
    o.z = f22h(b.x, b.y);
    o.w = f22h(b.z, b.w);
    out[i] = o;
}

// ---------------------------------------------------------------------------
// GEMM1 (TN): L[n][c][t] = sum_d (Q*SCALE)[d][c] * K[d][t]   (fp16 mma)
// Inputs pre-converted half2 pair-interleaved. cp.async 4-stage pipeline.
// CTA 256(c) x 128(t), warps 4(m)x2(n) of 64x64, KC=32 k (16 pairs/chunk).
// smem per stage: A [16][264]w (1056B rows) + B [16][136]w (544B rows).
// Pitches mod 32 == 8 -> conflict-free fragment LDS (R7-proven).
// ---------------------------------------------------------------------------
#define S1      25600                 // 16896 + 8704
#define SMEM1   (4 * S1)              // 102400

__global__ __launch_bounds__(256, 1) void gemm_qk(
    const uint32_t* __restrict__ Qh, const uint32_t* __restrict__ Kh,
    float* __restrict__ L)
{
    extern __shared__ char sm[];
    const uint32_t sb = smem_u32(sm);

    const int tid  = threadIdx.x;
    const int wid  = tid >> 5;
    const int lane = tid & 31;
    const int g    = lane >> 2;
    const int tig  = lane & 3;
    const int mOff = (wid >> 1) * 64;
    const int nOff = (wid & 1) * 64;

    const int n  = blockIdx.z;
    const uint32_t* Qn = Qh + (size_t)n * (DIM/2) * CQ;
    const uint32_t* Kn = Kh + (size_t)n * (DIM/2) * TT;
    float*          Lb = L  + (size_t)n * CQ * TT;
    const int c0 = blockIdx.y * 256;
    const int t0 = blockIdx.x * 128;

    // loaders: pair-row pr = tid/16 (0..15), 16-col A span / 8-col B span
    const int pr = tid >> 4;
    const int lc = tid & 15;
    const uint32_t* qsrc = Qn + (size_t)pr * CQ + c0 + lc * 16;
    const uint32_t* ksrc = Kn + (size_t)pr * TT + t0 + lc * 8;
    const uint32_t adst = sb + (uint32_t)(pr * 1056 + lc * 64);
    const uint32_t bdst = sb + 16896u + (uint32_t)(pr * 544 + lc * 32);

    float acc[4][8][4];
    #pragma unroll
    for (int i = 0; i < 4; i++)
        #pragma unroll
        for (int j = 0; j < 8; j++)
            #pragma unroll
            for (int r = 0; r < 4; r++) acc[i][j][r] = 0.f;

    // prologue: stages 0..2
    #pragma unroll
    for (int s = 0; s < 3; s++) {
        #pragma unroll
        for (int q = 0; q < 4; q++)
            cp16(adst + s * S1 + q * 16, qsrc + (size_t)s * 16 * CQ + q * 4);
        #pragma unroll
        for (int q = 0; q < 2; q++)
            cp16(bdst + s * S1 + q * 16, ksrc + (size_t)s * 16 * TT + q * 4);
        asm volatile("cp.async.commit_group;" ::: "memory");
    }

    for (int c = 0; c < 16; c++) {
        asm volatile("cp.async.wait_group 2;" ::: "memory");
        __syncthreads();

        // issue stage c+3
        {
            const int s = c + 3;
            if (s < 16) {
                #pragma unroll
                for (int q = 0; q < 4; q++)
                    cp16(adst + (s & 3) * S1 + q * 16, qsrc + (size_t)s * 16 * CQ + q * 4);
                #pragma unroll
                for (int q = 0; q < 2; q++)
                    cp16(bdst + (s & 3) * S1 + q * 16, ksrc + (size_t)s * 16 * TT + q * 4);
            }
            asm volatile("cp.async.commit_group;" ::: "memory");
        }

        const uint32_t* As = (const uint32_t*)(sm + (c & 3) * S1);
        const uint32_t* Bs = (const uint32_t*)(sm + (c & 3) * S1 + 16896);

        #pragma unroll
        for (int ks = 0; ks < 2; ks++) {
            const int kk = ks * 8;
            uint32_t a[4][4];
            #pragma unroll
            for (int i = 0; i < 4; i++) {
                const int mb = mOff + 16 * i;
                a[i][0] = As[(kk + tig    ) * 264 + mb + g    ];
                a[i][1] = As[(kk + tig    ) * 264 + mb + g + 8];
                a[i][2] = As[(kk + tig + 4) * 264 + mb + g    ];
                a[i][3] = As[(kk + tig + 4) * 264 + mb + g + 8];
            }
            uint32_t b[8][2];
            #pragma unroll
            for (int j = 0; j < 8; j++) {
                const int nb = nOff + 8 * j + g;
                b[j][0] = Bs[(kk + tig    ) * 136 + nb];
                b[j][1] = Bs[(kk + tig + 4) * 136 + nb];
            }
            #pragma unroll
            for (int i = 0; i < 4; i++)
                #pragma unroll
                for (int j = 0; j < 8; j++)
                    mma_f16(acc[i][j], a[i][0], a[i][1], a[i][2], a[i][3],
                            b[j][0], b[j][1]);
        }
    }

    #pragma unroll
    for (int i = 0; i < 4; i++) {
        const int row0 = c0 + mOff + 16 * i + g;
        #pragma unroll
        for (int j = 0; j < 8; j++) {
            const int colb = t0 + nOff + 8 * j + 2 * tig;
            *(float2*)(Lb + (size_t)row0 * TT + colb) =
                make_float2(acc[i][j][0], acc[i][j][1]);
            *(float2*)(Lb + (size_t)(row0 + 8) * TT + colb) =
                make_float2(acc[i][j][2], acc[i][j][3]);
        }
    }
}

// ---------------------------------------------------------------------------
// Fused mask + softmax over t; fp32 logits in, HALF weights out.
// ---------------------------------------------------------------------------
__global__ __launch_bounds__(256) void softmax_mask_kernel(
    const float* __restrict__ L, __half* __restrict__ Wh,
    const float* __restrict__ ratios)
{
    const int row = blockIdx.x;
    const int n   = row >> 9;
    const float* p = L + (size_t)row * TT;

    const float ratio = ratios[n];
    int vw = (int)floorf((float)WW * ratio + 0.5f);
    vw = vw > WW ? WW : vw;

    const int tid  = threadIdx.x;
    const int base = tid << 2;
    float4 v = ((const float4*)p)[tid];
    float vals[4] = {v.x, v.y, v.z, v.w};
    #pragma unroll
    for (int i = 0; i < 4; i++) {
        int wi = (base + i) & (WW - 1);
        if (wi >= vw) vals[i] = -INFINITY;
    }

    __shared__ float red_max[8];
    __shared__ float red_sum[8];
    const int lane = tid & 31;
    const int warp = tid >> 5;

    float m = fmaxf(fmaxf(vals[0], vals[1]), fmaxf(vals[2], vals[3]));
    #pragma unroll
    for (int off = 16; off > 0; off >>= 1)
        m = fmaxf(m, __shfl_xor_sync(0xffffffffu, m, off));
    if (lane == 0) red_max[warp] = m;
    __syncthreads();
    float mall = red_max[0];
    #pragma unroll
    for (int i = 1; i < 8; i++) mall = fmaxf(mall, red_max[i]);

    float s = 0.f;
    #pragma unroll
    for (int i = 0; i < 4; i++) {
        vals[i] = expf(vals[i] - mall);
        s += vals[i];
    }
    #pragma unroll
    for (int off = 16; off > 0; off >>= 1)
        s += __shfl_xor_sync(0xffffffffu, s, off);
    if (lane == 0) red_sum[warp] = s;
    __syncthreads();
    float sall = 0.f;
    #pragma unroll
    for (int i = 0; i < 8; i++) sall += red_sum[i];

    const float inv = 1.0f / sall;
    uint2 o;
    o.x = f22h(vals[0] * inv, vals[1] * inv);
    o.y = f22h(vals[2] * inv, vals[3] * inv);
    ((uint2*)(Wh + (size_t)row * TT))[tid] = o;
}

// ---------------------------------------------------------------------------
// GEMM2 (NT): O[n][d][c] = sum_t V[d][t] * W[c][t]   (fp16 mma)
// V and W half in gmem (t-pairs are half2 words). cp.async 4-stage.
// CTA 256(d) x 128(c), warps 4x2 of 64x64, KC=32 t (16 pairs/chunk).
// smem [x][kpair] pitch 20 words (80B) -> conflict-free (R7-proven).
// ---------------------------------------------------------------------------
#define S2      30720                 // 20480 + 10240
#define SMEM2   (4 * S2)              // 122880

__global__ __launch_bounds__(256, 1) void gemm_wv(
    const uint32_t* __restrict__ Vh, const uint32_t* __restrict__ Wp,
    float* __restrict__ O)
{
    extern __shared__ char sm[];
    const uint32_t sb = smem_u32(sm);

    const int tid  = threadIdx.x;
    const int wid  = tid >> 5;
    const int lane = tid & 31;
    const int g    = lane >> 2;
    const int tig  = lane & 3;
    const int mOff = (wid >> 1) * 64;
    const int nOff = (wid & 1) * 64;

    const int n  = blockIdx.z;
    const uint32_t* Vn = Vh + (size_t)n * DIM * (TT/2);
    const uint32_t* Wn = Wp + (size_t)n * CQ  * (TT/2);
    float*          Ob = O  + (size_t)n * DIM * CQ;
    const int d0 = blockIdx.y * 256;
    const int c0 = blockIdx.x * 128;

    // A loader: one d-row per thread, 16 words (4 chunks) per stage
    const uint32_t* vsrc = Vn + (size_t)(d0 + tid) * (TT/2);
    const uint32_t adst = sb + 20480u * 0 + (uint32_t)(tid * 80);
    // B loader: 2 threads per c-row, 8 words (2 chunks) each
    const int brow = tid >> 1;
    const int bseg = tid & 1;
    const uint32_t* wsrc = Wn + (size_t)(c0 + brow) * (TT/2) + bseg * 8;
    const uint32_t bdst = sb + 20480u + (uint32_t)(brow * 80 + bseg * 32);

    float acc[4][8][4];
    #pragma unroll
    for (int i = 0; i < 4; i++)
        #pragma unroll
        for (int j = 0; j < 8; j++)
            #pragma unroll
            for (int r = 0; r < 4; r++) acc[i][j][r] = 0.f;

    #pragma unroll
    for (int s = 0; s < 3; s++) {
        #pragma unroll
        for (int q = 0; q < 4; q++)
            cp16(adst + s * S2 + q * 16, vsrc + s * 16 + q * 4);
        #pragma unroll
        for (int q = 0; q < 2; q++)
            cp16(bdst + s * S2 + q * 16, wsrc + s * 16 + q * 4);
        asm volatile("cp.async.commit_group;" ::: "memory");
    }

    for (int c = 0; c < 32; c++) {
        asm volatile("cp.async.wait_group 2;" ::: "memory");
        __syncthreads();

        {
            const int s = c + 3;
            if (s < 32) {
                #pragma unroll
                for (int q = 0; q < 4; q++)
                    cp16(adst + (s & 3) * S2 + q * 16, vsrc + s * 16 + q * 4);
                #pragma unroll
                for (int q = 0; q < 2; q++)
                    cp16(bdst + (s & 3) * S2 + q * 16, wsrc + s * 16 + q * 4);
            }
            asm volatile("cp.async.commit_group;" ::: "memory");
        }

        const uint32_t* As = (const uint32_t*)(sm + (c & 3) * S2);
        const uint32_t* Bs = (const uint32_t*)(sm + (c & 3) * S2 + 20480);

        #pragma unroll
        for (int ks = 0; ks < 2; ks++) {
            const int kk = ks * 8;
            uint32_t a[4][4];
            #pragma unroll
            for (int i = 0; i < 4; i++) {
                const int mb = mOff + 16 * i;
                a[i][0] = As[(mb + g    ) * 20 + kk + tig    ];
                a[i][1] = As[(mb + g + 8) * 20 + kk + tig    ];
                a[i][2] = As[(mb + g    ) * 20 + kk + tig + 4];
                a[i][3] = As[(mb + g + 8) * 20 + kk + tig + 4];
            }
            uint32_t b[8][2];
            #pragma unroll
            for (int j = 0; j < 8; j++) {
                const int nb = nOff + 8 * j + g;
                b[j][0] = Bs[nb * 20 + kk + tig    ];
                b[j][1] = Bs[nb * 20 + kk + tig + 4];
            }
            #pragma unroll
            for (int i = 0; i < 4; i++)
                #pragma unroll
                for (int j = 0; j < 8; j++)
                    mma_f16(acc[i][j], a[i][0], a[i][1], a[i][2], a[i][3],
                            b[j][0], b[j][1]);
        }
    }

    #pragma unroll
    for (int i = 0; i < 4; i++) {
        const int row0 = d0 + mOff + 16 * i + g;
        #pragma unroll
        for (int j = 0; j < 8; j++) {
            const int colb = c0 + nOff + 8 * j + 2 * tig;
            *(float2*)(Ob + (size_t)row0 * CQ + colb) =
                make_float2(acc[i][j][0], acc[i][j][1]);
            *(float2*)(Ob + (size_t)(row0 + 8) * CQ + colb) =
                make_float2(acc[i][j][2], acc[i][j][3]);
        }
    }
}

// ---------------------------------------------------------------------------
extern "C" void kernel_launch(void* const* d_in, const int* in_sizes, int n_in,
                              void* d_out, int out_size)
{
    const float* query  = (const float*)d_in[0];  // [64, 512, 512]
    const float* key    = (const float*)d_in[1];  // [64, 512, 1024]
    const float* value  = (const float*)d_in[2];  // [64, 512, 1024]
    const float* ratios = (const float*)d_in[3];  // [64]
    float* out = (float*)d_out;                   // [64, 512, 512]

    float*    logits = nullptr;
    __half*   wh     = nullptr;
    uint32_t *qh = nullptr, *kh = nullptr, *vh = nullptr;
    cudaGetSymbolAddress((void**)&logits, g_logits);
    cudaGetSymbolAddress((void**)&wh, g_wh);
    cudaGetSymbolAddress((void**)&qh, g_qh);
    cudaGetSymbolAddress((void**)&kh, g_kh);
    cudaGetSymbolAddress((void**)&vh, g_vh);

    cudaFuncSetAttribute(gemm_qk, cudaFuncAttributeMaxDynamicSharedMemorySize, SMEM1);
    cudaFuncSetAttribute(gemm_wv, cudaFuncAttributeMaxDynamicSharedMemorySize, SMEM2);

    // 0) conversions
    pairify<<<dim3(CQ / 512, DIM / 2, N_BATCH), 128>>>(query, qh, CQ, SCALE);
    pairify<<<dim3(TT / 512, DIM / 2, N_BATCH), 128>>>(key,   kh, TT, 1.0f);
    {
        const size_t n8 = (size_t)N_BATCH * DIM * TT / 8;   // threads (8 floats each)
        vconv<<<(unsigned)(n8 / 256), 256>>>((const float4*)value, (uint4*)vh);
    }
    // 1) logits = (Q*SCALE)^T K
    {
        dim3 grid(TT / 128, CQ / 256, N_BATCH);  // (8, 2, 64)
        gemm_qk<<<grid, 256, SMEM1>>>(qh, kh, logits);
    }
    // 2) mask + softmax -> half weights
    softmax_mask_kernel<<<N_BATCH * CQ, 256>>>(logits, wh, ratios);
    // 3) out = V x W^T
    {
        dim3 grid(CQ / 128, DIM / 256, N_BATCH);  // (4, 2, 64)
        gemm_wv<<<grid, 256, SMEM2>>>(vh, (const uint32_t*)wh, out);
    }
}

// round 9
// speedup vs baseline: 1.9280x; 1.1694x over previous
#include <cuda_runtime.h>
#include <cuda_fp16.h>
#include <cstdint>
#include <math.h>

#define N_BATCH 64
#define DIM     512
#define CQ      512
#define TT      1024
#define WW      128
#define SCALE   0.04419417382415922f  // 512^-0.5

// Scratch (device globals)
static __device__ float    g_logits[(size_t)N_BATCH * CQ * TT];        // 128 MB
static __device__ __half   g_wh[(size_t)N_BATCH * CQ * TT];            // 64 MB weights (half)
static __device__ uint32_t g_qh[(size_t)N_BATCH * (DIM/2) * CQ];       // 32 MB Q pair-interleaved half2
static __device__ uint32_t g_kh[(size_t)N_BATCH * (DIM/2) * TT];       // 64 MB K pair-interleaved half2
static __device__ uint32_t g_vh[(size_t)N_BATCH * DIM * (TT/2)];       // 64 MB V half (t-pairs)

// ---------------------------------------------------------------------------
__device__ __forceinline__ uint32_t smem_u32(const void* p) {
    uint32_t a;
    asm("{ .reg .u64 t; cvta.to.shared.u64 t, %1; cvt.u32.u64 %0, t; }"
        : "=r"(a) : "l"(p));
    return a;
}

__device__ __forceinline__ uint32_t f22h(float x, float y) {
    __half2 h = __floats2half2_rn(x, y);
    return *(uint32_t*)&h;
}

__device__ __forceinline__ void mma_f16(float c[4],
                                        uint32_t a0, uint32_t a1, uint32_t a2, uint32_t a3,
                                        uint32_t b0, uint32_t b1) {
    asm volatile(
        "mma.sync.aligned.m16n8k16.row.col.f32.f16.f16.f32 "
        "{%0,%1,%2,%3}, {%4,%5,%6,%7}, {%8,%9}, {%0,%1,%2,%3};"
        : "+f"(c[0]), "+f"(c[1]), "+f"(c[2]), "+f"(c[3])
        : "r"(a0), "r"(a1), "r"(a2), "r"(a3), "r"(b0), "r"(b1));
}

__device__ __forceinline__ void cp16(uint32_t saddr, const void* gaddr) {
    asm volatile("cp.async.cg.shared.global [%0], [%1], 16;"
        :: "r"(saddr), "l"(gaddr) : "memory");
}

// ---------------------------------------------------------------------------
// Conversion passes
// ---------------------------------------------------------------------------
__global__ __launch_bounds__(128) void pairify(
    const float* __restrict__ in, uint32_t* __restrict__ out,
    int W, float mul)
{
    const int n   = blockIdx.z;
    const int p   = blockIdx.y;
    const int P   = gridDim.y;        // DIM/2
    const int col = (blockIdx.x * 128 + threadIdx.x) * 4;

    const float* r0 = in + ((size_t)n * 2 * P + 2 * p) * W + col;
    const float* r1 = r0 + W;
    float4 a = *(const float4*)r0;
    float4 b = *(const float4*)r1;
    uint4 o;
    o.x = f22h(a.x * mul, b.x * mul);
    o.y = f22h(a.y * mul, b.y * mul);
    o.z = f22h(a.z * mul, b.z * mul);
    o.w = f22h(a.w * mul, b.w * mul);
    *(uint4*)(out + ((size_t)n * P + p) * W + col) = o;
}

__global__ __launch_bounds__(256) void vconv(
    const float4* __restrict__ in, uint4* __restrict__ out)
{
    const size_t i = (size_t)blockIdx.x * 256 + threadIdx.x;
    float4 a = in[2 * i];
    float4 b = in[2 * i + 1];
    uint4 o;
    o.x = f22h(a.x, a.y);
    o.y = f22h(a.z, a.w);
    o.z = f22h(b.x, b.y);
    o.w = f22h(b.z, b.w);
    out[i] = o;
}

// ---------------------------------------------------------------------------
// GEMM1 (TN): L[n][c][t] = sum_d (Q*SCALE)[d][c] * K[d][t]   (fp16 mma)
// cp.async 4-stage + fragment register double-buffering.
// CTA 256(c) x 128(t), warps 4(m)x2(n) of 64x64, KC=32 k (16 pairs/chunk).
// ---------------------------------------------------------------------------
#define S1      25600                 // 16896 + 8704
#define SMEM1   (4 * S1)

__device__ __forceinline__ void g1_frags(
    const uint32_t* __restrict__ As, const uint32_t* __restrict__ Bs,
    int kk, int mOff, int nOff, int g, int tig,
    uint32_t a[4][4], uint32_t b[8][2])
{
    #pragma unroll
    for (int i = 0; i < 4; i++) {
        const int mb = mOff + 16 * i;
        a[i][0] = As[(kk + tig    ) * 264 + mb + g    ];
        a[i][1] = As[(kk + tig    ) * 264 + mb + g + 8];
        a[i][2] = As[(kk + tig + 4) * 264 + mb + g    ];
        a[i][3] = As[(kk + tig + 4) * 264 + mb + g + 8];
    }
    #pragma unroll
    for (int j = 0; j < 8; j++) {
        const int nb = nOff + 8 * j + g;
        b[j][0] = Bs[(kk + tig    ) * 136 + nb];
        b[j][1] = Bs[(kk + tig + 4) * 136 + nb];
    }
}

__device__ __forceinline__ void g_mmas(float acc[4][8][4],
                                       uint32_t a[4][4], uint32_t b[8][2])
{
    #pragma unroll
    for (int i = 0; i < 4; i++)
        #pragma unroll
        for (int j = 0; j < 8; j++)
            mma_f16(acc[i][j], a[i][0], a[i][1], a[i][2], a[i][3],
                    b[j][0], b[j][1]);
}

__global__ __launch_bounds__(256, 1) void gemm_qk(
    const uint32_t* __restrict__ Qh, const uint32_t* __restrict__ Kh,
    float* __restrict__ L)
{
    extern __shared__ char sm[];
    const uint32_t sb = smem_u32(sm);

    const int tid  = threadIdx.x;
    const int wid  = tid >> 5;
    const int lane = tid & 31;
    const int g    = lane >> 2;
    const int tig  = lane & 3;
    const int mOff = (wid >> 1) * 64;
    const int nOff = (wid & 1) * 64;

    const int n  = blockIdx.z;
    const uint32_t* Qn = Qh + (size_t)n * (DIM/2) * CQ;
    const uint32_t* Kn = Kh + (size_t)n * (DIM/2) * TT;
    float*          Lb = L  + (size_t)n * CQ * TT;
    const int c0 = blockIdx.y * 256;
    const int t0 = blockIdx.x * 128;

    const int pr = tid >> 4;
    const int lc = tid & 15;
    const uint32_t* qsrc = Qn + (size_t)pr * CQ + c0 + lc * 16;
    const uint32_t* ksrc = Kn + (size_t)pr * TT + t0 + lc * 8;
    const uint32_t adst = sb + (uint32_t)(pr * 1056 + lc * 64);
    const uint32_t bdst = sb + 16896u + (uint32_t)(pr * 544 + lc * 32);

    float acc[4][8][4];
    #pragma unroll
    for (int i = 0; i < 4; i++)
        #pragma unroll
        for (int j = 0; j < 8; j++)
            #pragma unroll
            for (int r = 0; r < 4; r++) acc[i][j][r] = 0.f;

    #pragma unroll
    for (int s = 0; s < 3; s++) {
        #pragma unroll
        for (int q = 0; q < 4; q++)
            cp16(adst + s * S1 + q * 16, qsrc + (size_t)s * 16 * CQ + q * 4);
        #pragma unroll
        for (int q = 0; q < 2; q++)
            cp16(bdst + s * S1 + q * 16, ksrc + (size_t)s * 16 * TT + q * 4);
        asm volatile("cp.async.commit_group;" ::: "memory");
    }

    asm volatile("cp.async.wait_group 2;" ::: "memory");
    __syncthreads();

    uint32_t af[2][4][4], bf[2][8][2];
    g1_frags((const uint32_t*)(sm), (const uint32_t*)(sm + 16896),
             0, mOff, nOff, g, tig, af[0], bf[0]);

    for (int c = 0; c < 16; c++) {
        const uint32_t* As = (const uint32_t*)(sm + (c & 3) * S1);
        const uint32_t* Bs = (const uint32_t*)(sm + (c & 3) * S1 + 16896);

        // prefetch ks=1 frags, then run ks=0 MMAs behind them
        g1_frags(As, Bs, 8, mOff, nOff, g, tig, af[1], bf[1]);
        g_mmas(acc, af[0], bf[0]);

        // issue stage c+3
        {
            const int s = c + 3;
            if (s < 16) {
                #pragma unroll
                for (int q = 0; q < 4; q++)
                    cp16(adst + (s & 3) * S1 + q * 16, qsrc + (size_t)s * 16 * CQ + q * 4);
                #pragma unroll
                for (int q = 0; q < 2; q++)
                    cp16(bdst + (s & 3) * S1 + q * 16, ksrc + (size_t)s * 16 * TT + q * 4);
            }
            asm volatile("cp.async.commit_group;" ::: "memory");
        }
        asm volatile("cp.async.wait_group 2;" ::: "memory");
        __syncthreads();

        // prefetch next chunk ks=0 frags, then run ks=1 MMAs behind them
        if (c + 1 < 16) {
            const uint32_t* An = (const uint32_t*)(sm + ((c + 1) & 3) * S1);
            const uint32_t* Bn = (const uint32_t*)(sm + ((c + 1) & 3) * S1 + 16896);
            g1_frags(An, Bn, 0, mOff, nOff, g, tig, af[0], bf[0]);
        }
        g_mmas(acc, af[1], bf[1]);
    }

    #pragma unroll
    for (int i = 0; i < 4; i++) {
        const int row0 = c0 + mOff + 16 * i + g;
        #pragma unroll
        for (int j = 0; j < 8; j++) {
            const int colb = t0 + nOff + 8 * j + 2 * tig;
            *(float2*)(Lb + (size_t)row0 * TT + colb) =
                make_float2(acc[i][j][0], acc[i][j][1]);
            *(float2*)(Lb + (size_t)(row0 + 8) * TT + colb) =
                make_float2(acc[i][j][2], acc[i][j][3]);
        }
    }
}

// ---------------------------------------------------------------------------
// Fused mask + softmax over t; fp32 logits in, HALF weights out.
// ---------------------------------------------------------------------------
__global__ __launch_bounds__(256) void softmax_mask_kernel(
    const float* __restrict__ L, __half* __restrict__ Wh,
    const float* __restrict__ ratios)
{
    const int row = blockIdx.x;
    const int n   = row >> 9;
    const float* p = L + (size_t)row * TT;

    const float ratio = ratios[n];
    int vw = (int)floorf((float)WW * ratio + 0.5f);
    vw = vw > WW ? WW : vw;

    const int tid  = threadIdx.x;
    const int base = tid << 2;
    float4 v = ((const float4*)p)[tid];
    float vals[4] = {v.x, v.y, v.z, v.w};
    #pragma unroll
    for (int i = 0; i < 4; i++) {
        int wi = (base + i) & (WW - 1);
        if (wi >= vw) vals[i] = -INFINITY;
    }

    __shared__ float red_max[8];
    __shared__ float red_sum[8];
    const int lane = tid & 31;
    const int warp = tid >> 5;

    float m = fmaxf(fmaxf(vals[0], vals[1]), fmaxf(vals[2], vals[3]));
    #pragma unroll
    for (int off = 16; off > 0; off >>= 1)
        m = fmaxf(m, __shfl_xor_sync(0xffffffffu, m, off));
    if (lane == 0) red_max[warp] = m;
    __syncthreads();
    float mall = red_max[0];
    #pragma unroll
    for (int i = 1; i < 8; i++) mall = fmaxf(mall, red_max[i]);

    float s = 0.f;
    #pragma unroll
    for (int i = 0; i < 4; i++) {
        vals[i] = expf(vals[i] - mall);
        s += vals[i];
    }
    #pragma unroll
    for (int off = 16; off > 0; off >>= 1)
        s += __shfl_xor_sync(0xffffffffu, s, off);
    if (lane == 0) red_sum[warp] = s;
    __syncthreads();
    float sall = 0.f;
    #pragma unroll
    for (int i = 0; i < 8; i++) sall += red_sum[i];

    const float inv = 1.0f / sall;
    uint2 o;
    o.x = f22h(vals[0] * inv, vals[1] * inv);
    o.y = f22h(vals[2] * inv, vals[3] * inv);
    ((uint2*)(Wh + (size_t)row * TT))[tid] = o;
}

// ---------------------------------------------------------------------------
// GEMM2 (NT): O[n][d][c] = sum_t V[d][t] * W[c][t]   (fp16 mma)
// cp.async 4-stage + fragment register double-buffering.
// CTA 256(d) x 128(c), warps 4x2 of 64x64, KC=32 t (16 pairs/chunk).
// ---------------------------------------------------------------------------
#define S2      30720                 // 20480 + 10240
#define SMEM2   (4 * S2)

__device__ __forceinline__ void g2_frags(
    const uint32_t* __restrict__ As, const uint32_t* __restrict__ Bs,
    int kk, int mOff, int nOff, int g, int tig,
    uint32_t a[4][4], uint32_t b[8][2])
{
    #pragma unroll
    for (int i = 0; i < 4; i++) {
        const int mb = mOff + 16 * i;
        a[i][0] = As[(mb + g    ) * 20 + kk + tig    ];
        a[i][1] = As[(mb + g + 8) * 20 + kk + tig    ];
        a[i][2] = As[(mb + g    ) * 20 + kk + tig + 4];
        a[i][3] = As[(mb + g + 8) * 20 + kk + tig + 4];
    }
    #pragma unroll
    for (int j = 0; j < 8; j++) {
        const int nb = nOff + 8 * j + g;
        b[j][0] = Bs[nb * 20 + kk + tig    ];
        b[j][1] = Bs[nb * 20 + kk + tig + 4];
    }
}

__global__ __launch_bounds__(256, 1) void gemm_wv(
    const uint32_t* __restrict__ Vh, const uint32_t* __restrict__ Wp,
    float* __restrict__ O)
{
    extern __shared__ char sm[];
    const uint32_t sb = smem_u32(sm);

    const int tid  = threadIdx.x;
    const int wid  = tid >> 5;
    const int lane = tid & 31;
    const int g    = lane >> 2;
    const int tig  = lane & 3;
    const int mOff = (wid >> 1) * 64;
    const int nOff = (wid & 1) * 64;

    const int n  = blockIdx.z;
    const uint32_t* Vn = Vh + (size_t)n * DIM * (TT/2);
    const uint32_t* Wn = Wp + (size_t)n * CQ  * (TT/2);
    float*          Ob = O  + (size_t)n * DIM * CQ;
    const int d0 = blockIdx.y * 256;
    const int c0 = blockIdx.x * 128;

    const uint32_t* vsrc = Vn + (size_t)(d0 + tid) * (TT/2);
    const uint32_t adst = sb + (uint32_t)(tid * 80);
    const int brow = tid >> 1;
    const int bseg = tid & 1;
    const uint32_t* wsrc = Wn + (size_t)(c0 + brow) * (TT/2) + bseg * 8;
    const uint32_t bdst = sb + 20480u + (uint32_t)(brow * 80 + bseg * 32);

    float acc[4][8][4];
    #pragma unroll
    for (int i = 0; i < 4; i++)
        #pragma unroll
        for (int j = 0; j < 8; j++)
            #pragma unroll
            for (int r = 0; r < 4; r++) acc[i][j][r] = 0.f;

    #pragma unroll
    for (int s = 0; s < 3; s++) {
        #pragma unroll
        for (int q = 0; q < 4; q++)
            cp16(adst + s * S2 + q * 16, vsrc + s * 16 + q * 4);
        #pragma unroll
        for (int q = 0; q < 2; q++)
            cp16(bdst + s * S2 + q * 16, wsrc + s * 16 + q * 4);
        asm volatile("cp.async.commit_group;" ::: "memory");
    }

    asm volatile("cp.async.wait_group 2;" ::: "memory");
    __syncthreads();

    uint32_t af[2][4][4], bf[2][8][2];
    g2_frags((const uint32_t*)(sm), (const uint32_t*)(sm + 20480),
             0, mOff, nOff, g, tig, af[0], bf[0]);

    for (int c = 0; c < 32; c++) {
        const uint32_t* As = (const uint32_t*)(sm + (c & 3) * S2);
        const uint32_t* Bs = (const uint32_t*)(sm + (c & 3) * S2 + 20480);

        g2_frags(As, Bs, 8, mOff, nOff, g, tig, af[1], bf[1]);
        g_mmas(acc, af[0], bf[0]);

        {
            const int s = c + 3;
            if (s < 32) {
                #pragma unroll
                for (int q = 0; q < 4; q++)
                    cp16(adst + (s & 3) * S2 + q * 16, vsrc + s * 16 + q * 4);
                #pragma unroll
                for (int q = 0; q < 2; q++)
                    cp16(bdst + (s & 3) * S2 + q * 16, wsrc + s * 16 + q * 4);
            }
            asm volatile("cp.async.commit_group;" ::: "memory");
        }
        asm volatile("cp.async.wait_group 2;" ::: "memory");
        __syncthreads();

        if (c + 1 < 32) {
            const uint32_t* An = (const uint32_t*)(sm + ((c + 1) & 3) * S2);
            const uint32_t* Bn = (const uint32_t*)(sm + ((c + 1) & 3) * S2 + 20480);
            g2_frags(An, Bn, 0, mOff, nOff, g, tig, af[0], bf[0]);
        }
        g_mmas(acc, af[1], bf[1]);
    }

    #pragma unroll
    for (int i = 0; i < 4; i++) {
        const int row0 = d0 + mOff + 16 * i + g;
        #pragma unroll
        for (int j = 0; j < 8; j++) {
            const int colb = c0 + nOff + 8 * j + 2 * tig;
            *(float2*)(Ob + (size_t)row0 * CQ + colb) =
                make_float2(acc[i][j][0], acc[i][j][1]);
            *(float2*)(Ob + (size_t)(row0 + 8) * CQ + colb) =
                make_float2(acc[i][j][2], acc[i][j][3]);
        }
    }
}

// ---------------------------------------------------------------------------
extern "C" void kernel_launch(void* const* d_in, const int* in_sizes, int n_in,
                              void* d_out, int out_size)
{
    const float* query  = (const float*)d_in[0];  // [64, 512, 512]
    const float* key    = (const float*)d_in[1];  // [64, 512, 1024]
    const float* value  = (const float*)d_in[2];  // [64, 512, 1024]
    const float* ratios = (const float*)d_in[3];  // [64]
    float* out = (float*)d_out;                   // [64, 512, 512]

    float*    logits = nullptr;
    __half*   wh     = nullptr;
    uint32_t *qh = nullptr, *kh = nullptr, *vh = nullptr;
    cudaGetSymbolAddress((void**)&logits, g_logits);
    cudaGetSymbolAddress((void**)&wh, g_wh);
    cudaGetSymbolAddress((void**)&qh, g_qh);
    cudaGetSymbolAddress((void**)&kh, g_kh);
    cudaGetSymbolAddress((void**)&vh, g_vh);

    cudaFuncSetAttribute(gemm_qk, cudaFuncAttributeMaxDynamicSharedMemorySize, SMEM1);
    cudaFuncSetAttribute(gemm_wv, cudaFuncAttributeMaxDynamicSharedMemorySize, SMEM2);

    // 0) conversions
    pairify<<<dim3(CQ / 512, DIM / 2, N_BATCH), 128>>>(query, qh, CQ, SCALE);
    pairify<<<dim3(TT / 512, DIM / 2, N_BATCH), 128>>>(key,   kh, TT, 1.0f);
    {
        const size_t n8 = (size_t)N_BATCH * DIM * TT / 8;
        vconv<<<(unsigned)(n8 / 256), 256>>>((const float4*)value, (uint4*)vh);
    }
    // 1) logits = (Q*SCALE)^T K
    {
        dim3 grid(TT / 128, CQ / 256, N_BATCH);  // (8, 2, 64)
        gemm_qk<<<grid, 256, SMEM1>>>(qh, kh, logits);
    }
    // 2) mask + softmax -> half weights
    softmax_mask_kernel<<<N_BATCH * CQ, 256>>>(logits, wh, ratios);
    // 3) out = V x W^T
    {
        dim3 grid(CQ / 128, DIM / 256, N_BATCH);  // (4, 2, 64)
        gemm_wv<<<grid, 256, SMEM2>>>(vh, (const uint32_t*)wh, out);
    }
}

// round 10
// speedup vs baseline: 2.0929x; 1.0855x over previous
#include <cuda_runtime.h>
#include <cuda_fp16.h>
#include <cstdint>
#include <math.h>

#define N_BATCH 64
#define DIM     512
#define CQ      512
#define TT      1024
#define WW      128
#define SCALE   0.04419417382415922f  // 512^-0.5

// Scratch (device globals)
static __device__ __half   g_wh[(size_t)N_BATCH * CQ * TT];         // 64 MB unnormalized exp (half)
static __device__ uint32_t g_qh[(size_t)N_BATCH * (DIM/2) * CQ];    // 32 MB Q pair-interleaved half2 (scaled)
static __device__ uint32_t g_kh[(size_t)N_BATCH * (DIM/2) * TT];    // 64 MB K pair-interleaved half2
static __device__ uint32_t g_vh[(size_t)N_BATCH * DIM * (TT/2)];    // 64 MB V half (t-pairs)
static __device__ float    g_Spart[16 * N_BATCH * CQ];              // 2 MB partial row sums
static __device__ float    g_Sinv[N_BATCH * CQ];                    // 128 KB reciprocal sums

// ---------------------------------------------------------------------------
__device__ __forceinline__ uint32_t smem_u32(const void* p) {
    uint32_t a;
    asm("{ .reg .u64 t; cvta.to.shared.u64 t, %1; cvt.u32.u64 %0, t; }"
        : "=r"(a) : "l"(p));
    return a;
}

__device__ __forceinline__ uint32_t f22h(float x, float y) {
    __half2 h = __floats2half2_rn(x, y);
    return *(uint32_t*)&h;
}

__device__ __forceinline__ void mma_f16(float c[4],
                                        uint32_t a0, uint32_t a1, uint32_t a2, uint32_t a3,
                                        uint32_t b0, uint32_t b1) {
    asm volatile(
        "mma.sync.aligned.m16n8k16.row.col.f32.f16.f16.f32 "
        "{%0,%1,%2,%3}, {%4,%5,%6,%7}, {%8,%9}, {%0,%1,%2,%3};"
        : "+f"(c[0]), "+f"(c[1]), "+f"(c[2]), "+f"(c[3])
        : "r"(a0), "r"(a1), "r"(a2), "r"(a3), "r"(b0), "r"(b1));
}

__device__ __forceinline__ void cp16(uint32_t saddr, const void* gaddr) {
    asm volatile("cp.async.cg.shared.global [%0], [%1], 16;"
        :: "r"(saddr), "l"(gaddr) : "memory");
}

// ---------------------------------------------------------------------------
// Conversion passes
// ---------------------------------------------------------------------------
__global__ __launch_bounds__(128) void pairify(
    const float* __restrict__ in, uint32_t* __restrict__ out,
    int W, float mul)
{
    const int n   = blockIdx.z;
    const int p   = blockIdx.y;
    const int P   = gridDim.y;
    const int col = (blockIdx.x * 128 + threadIdx.x) * 4;

    const float* r0 = in + ((size_t)n * 2 * P + 2 * p) * W + col;
    const float* r1 = r0 + W;
    float4 a = *(const float4*)r0;
    float4 b = *(const float4*)r1;
    uint4 o;
    o.x = f22h(a.x * mul, b.x * mul);
    o.y = f22h(a.y * mul, b.y * mul);
    o.z = f22h(a.z * mul, b.z * mul);
    o.w = f22h(a.w * mul, b.w * mul);
    *(uint4*)(out + ((size_t)n * P + p) * W + col) = o;
}

__global__ __launch_bounds__(256) void vconv(
    const float4* __restrict__ in, uint4* __restrict__ out)
{
    const size_t i = (size_t)blockIdx.x * 256 + threadIdx.x;
    float4 a = in[2 * i];
    float4 b = in[2 * i + 1];
    uint4 o;
    o.x = f22h(a.x, a.y);
    o.y = f22h(a.z, a.w);
    o.z = f22h(b.x, b.y);
    o.w = f22h(b.z, b.w);
    out[i] = o;
}

// ---------------------------------------------------------------------------
// GEMM1 (TN) + masked exp epilogue:
//   e[n][c][t] = mask ? exp((Q*SCALE)^T K) : 0   (half, unnormalized)
//   Spart[slot][n][c] = partial row sums (deterministic slots)
// CTA 256(c) x 128(t), warps 4(m)x2(n) of 64x64, KC=32, 4-stage cp.async,
// fragment register double-buffering. slot = blockIdx.x*2 + (wid&1).
// ---------------------------------------------------------------------------
#define S1      25600                 // 16896 + 8704
#define SMEM1   (4 * S1)

__device__ __forceinline__ void g1_frags(
    const uint32_t* __restrict__ As, const uint32_t* __restrict__ Bs,
    int kk, int mOff, int nOff, int g, int tig,
    uint32_t a[4][4], uint32_t b[8][2])
{
    #pragma unroll
    for (int i = 0; i < 4; i++) {
        const int mb = mOff + 16 * i;
        a[i][0] = As[(kk + tig    ) * 264 + mb + g    ];
        a[i][1] = As[(kk + tig    ) * 264 + mb + g + 8];
        a[i][2] = As[(kk + tig + 4) * 264 + mb + g    ];
        a[i][3] = As[(kk + tig + 4) * 264 + mb + g + 8];
    }
    #pragma unroll
    for (int j = 0; j < 8; j++) {
        const int nb = nOff + 8 * j + g;
        b[j][0] = Bs[(kk + tig    ) * 136 + nb];
        b[j][1] = Bs[(kk + tig + 4) * 136 + nb];
    }
}

__device__ __forceinline__ void g_mmas8(float acc[4][8][4],
                                        uint32_t a[4][4], uint32_t b[8][2])
{
    #pragma unroll
    for (int i = 0; i < 4; i++)
        #pragma unroll
        for (int j = 0; j < 8; j++)
            mma_f16(acc[i][j], a[i][0], a[i][1], a[i][2], a[i][3],
                    b[j][0], b[j][1]);
}

__global__ __launch_bounds__(256, 1) void gemm_qk(
    const uint32_t* __restrict__ Qh, const uint32_t* __restrict__ Kh,
    __half* __restrict__ Wh, float* __restrict__ Spart,
    const float* __restrict__ ratios)
{
    extern __shared__ char sm[];
    const uint32_t sb = smem_u32(sm);

    const int tid  = threadIdx.x;
    const int wid  = tid >> 5;
    const int lane = tid & 31;
    const int g    = lane >> 2;
    const int tig  = lane & 3;
    const int mOff = (wid >> 1) * 64;
    const int nOff = (wid & 1) * 64;

    const int n  = blockIdx.z;
    const uint32_t* Qn = Qh + (size_t)n * (DIM/2) * CQ;
    const uint32_t* Kn = Kh + (size_t)n * (DIM/2) * TT;
    const int c0 = blockIdx.y * 256;
    const int t0 = blockIdx.x * 128;

    const int pr = tid >> 4;
    const int lc = tid & 15;
    const uint32_t* qsrc = Qn + (size_t)pr * CQ + c0 + lc * 16;
    const uint32_t* ksrc = Kn + (size_t)pr * TT + t0 + lc * 8;
    const uint32_t adst = sb + (uint32_t)(pr * 1056 + lc * 64);
    const uint32_t bdst = sb + 16896u + (uint32_t)(pr * 544 + lc * 32);

    float acc[4][8][4];
    #pragma unroll
    for (int i = 0; i < 4; i++)
        #pragma unroll
        for (int j = 0; j < 8; j++)
            #pragma unroll
            for (int r = 0; r < 4; r++) acc[i][j][r] = 0.f;

    #pragma unroll
    for (int s = 0; s < 3; s++) {
        #pragma unroll
        for (int q = 0; q < 4; q++)
            cp16(adst + s * S1 + q * 16, qsrc + (size_t)s * 16 * CQ + q * 4);
        #pragma unroll
        for (int q = 0; q < 2; q++)
            cp16(bdst + s * S1 + q * 16, ksrc + (size_t)s * 16 * TT + q * 4);
        asm volatile("cp.async.commit_group;" ::: "memory");
    }

    asm volatile("cp.async.wait_group 2;" ::: "memory");
    __syncthreads();

    uint32_t af[2][4][4], bf[2][8][2];
    g1_frags((const uint32_t*)(sm), (const uint32_t*)(sm + 16896),
             0, mOff, nOff, g, tig, af[0], bf[0]);

    for (int c = 0; c < 16; c++) {
        const uint32_t* As = (const uint32_t*)(sm + (c & 3) * S1);
        const uint32_t* Bs = (const uint32_t*)(sm + (c & 3) * S1 + 16896);

        g1_frags(As, Bs, 8, mOff, nOff, g, tig, af[1], bf[1]);
        g_mmas8(acc, af[0], bf[0]);

        {
            const int s = c + 3;
            if (s < 16) {
                #pragma unroll
                for (int q = 0; q < 4; q++)
                    cp16(adst + (s & 3) * S1 + q * 16, qsrc + (size_t)s * 16 * CQ + q * 4);
                #pragma unroll
                for (int q = 0; q < 2; q++)
                    cp16(bdst + (s & 3) * S1 + q * 16, ksrc + (size_t)s * 16 * TT + q * 4);
            }
            asm volatile("cp.async.commit_group;" ::: "memory");
        }
        asm volatile("cp.async.wait_group 2;" ::: "memory");
        __syncthreads();

        if (c + 1 < 16) {
            const uint32_t* An = (const uint32_t*)(sm + ((c + 1) & 3) * S1);
            const uint32_t* Bn = (const uint32_t*)(sm + ((c + 1) & 3) * S1 + 16896);
            g1_frags(An, Bn, 0, mOff, nOff, g, tig, af[0], bf[0]);
        }
        g_mmas8(acc, af[1], bf[1]);
    }

    // ---- epilogue: mask + exp + half store + deterministic partial sums ----
    const float ratio = ratios[n];
    int vw = (int)floorf((float)WW * ratio + 0.5f);
    vw = vw > WW ? WW : vw;

    uint32_t* Ww = (uint32_t*)(Wh + (size_t)n * CQ * TT);
    float rsum[4][2];
    #pragma unroll
    for (int i = 0; i < 4; i++) { rsum[i][0] = 0.f; rsum[i][1] = 0.f; }

    #pragma unroll
    for (int i = 0; i < 4; i++) {
        const int row0 = c0 + mOff + 16 * i + g;
        #pragma unroll
        for (int j = 0; j < 8; j++) {
            const int wc   = nOff + 8 * j + 2 * tig;   // t % 128 (t0 mult of 128)
            const int colb = t0 + wc;
            float e0 = (wc     < vw) ? __expf(acc[i][j][0]) : 0.f;
            float e1 = (wc + 1 < vw) ? __expf(acc[i][j][1]) : 0.f;
            float e2 = (wc     < vw) ? __expf(acc[i][j][2]) : 0.f;
            float e3 = (wc + 1 < vw) ? __expf(acc[i][j][3]) : 0.f;
            Ww[((size_t)row0 * TT + colb) >> 1]       = f22h(e0, e1);
            Ww[((size_t)(row0 + 8) * TT + colb) >> 1] = f22h(e2, e3);
            rsum[i][0] += e0 + e1;
            rsum[i][1] += e2 + e3;
        }
    }
    // reduce over tig (lanes 4g+tig)
    #pragma unroll
    for (int i = 0; i < 4; i++) {
        #pragma unroll
        for (int h = 0; h < 2; h++) {
            float v = rsum[i][h];
            v += __shfl_xor_sync(0xffffffffu, v, 1);
            v += __shfl_xor_sync(0xffffffffu, v, 2);
            rsum[i][h] = v;
        }
    }
    if (tig == 0) {
        const int slot = blockIdx.x * 2 + (wid & 1);
        float* sp = Spart + (size_t)slot * N_BATCH * CQ + (size_t)n * CQ;
        #pragma unroll
        for (int i = 0; i < 4; i++) {
            sp[c0 + mOff + 16 * i + g    ] = rsum[i][0];
            sp[c0 + mOff + 16 * i + g + 8] = rsum[i][1];
        }
    }
}

// ---------------------------------------------------------------------------
// Sinv[n][c] = 1 / sum_slot Spart[slot][n][c]   (deterministic order)
// ---------------------------------------------------------------------------
__global__ __launch_bounds__(256) void sinv_kernel(
    const float* __restrict__ Spart, float* __restrict__ Sinv)
{
    const int idx = blockIdx.x * 256 + threadIdx.x;   // 0..32767
    float s = 0.f;
    #pragma unroll
    for (int k = 0; k < 16; k++)
        s += Spart[(size_t)k * N_BATCH * CQ + idx];
    Sinv[idx] = 1.0f / s;
}

// ---------------------------------------------------------------------------
// GEMM2 (NT): O[n][d][c] = Sinv[c] * sum_t V[d][t] * e[c][t]   (fp16 mma)
// CTA 128(d) x 128(c) (1024 CTAs -> good wave balance), warps 2(m)x4(n) of
// 64x32, KC=32 t, 4-stage cp.async, frag double-buffer, pitch 20 words.
// ---------------------------------------------------------------------------
#define S2      20480                 // 10240 + 10240
#define SMEM2   (4 * S2)

__device__ __forceinline__ void g2_frags(
    const uint32_t* __restrict__ As, const uint32_t* __restrict__ Bs,
    int kk, int mOff, int nOff, int g, int tig,
    uint32_t a[4][4], uint32_t b[4][2])
{
    #pragma unroll
    for (int i = 0; i < 4; i++) {
        const int mb = mOff + 16 * i;
        a[i][0] = As[(mb + g    ) * 20 + kk + tig    ];
        a[i][1] = As[(mb + g + 8) * 20 + kk + tig    ];
        a[i][2] = As[(mb + g    ) * 20 + kk + tig + 4];
        a[i][3] = As[(mb + g + 8) * 20 + kk + tig + 4];
    }
    #pragma unroll
    for (int j = 0; j < 4; j++) {
        const int nb = nOff + 8 * j + g;
        b[j][0] = Bs[nb * 20 + kk + tig    ];
        b[j][1] = Bs[nb * 20 + kk + tig + 4];
    }
}

__device__ __forceinline__ void g_mmas4(float acc[4][4][4],
                                        uint32_t a[4][4], uint32_t b[4][2])
{
    #pragma unroll
    for (int i = 0; i < 4; i++)
        #pragma unroll
        for (int j = 0; j < 4; j++)
            mma_f16(acc[i][j], a[i][0], a[i][1], a[i][2], a[i][3],
                    b[j][0], b[j][1]);
}

__global__ __launch_bounds__(256, 1) void gemm_wv(
    const uint32_t* __restrict__ Vh, const uint32_t* __restrict__ Wp,
    const float* __restrict__ Sinv, float* __restrict__ O)
{
    extern __shared__ char sm[];
    const uint32_t sb = smem_u32(sm);

    const int tid  = threadIdx.x;
    const int wid  = tid >> 5;
    const int lane = tid & 31;
    const int g    = lane >> 2;
    const int tig  = lane & 3;
    const int mOff = (wid >> 2) * 64;   // 0,64
    const int nOff = (wid & 3) * 32;    // 0,32,64,96

    const int n  = blockIdx.z;
    const uint32_t* Vn = Vh + (size_t)n * DIM * (TT/2);
    const uint32_t* Wn = Wp + (size_t)n * CQ  * (TT/2);
    float*          Ob = O  + (size_t)n * DIM * CQ;
    const int d0 = blockIdx.y * 128;
    const int c0 = blockIdx.x * 128;

    // loaders: 2 threads per row, 8 words each (2 cp16) per stage
    const int lr  = tid >> 1;
    const int ls  = tid & 1;
    const uint32_t* vsrc = Vn + (size_t)(d0 + lr) * (TT/2) + ls * 8;
    const uint32_t* wsrc = Wn + (size_t)(c0 + lr) * (TT/2) + ls * 8;
    const uint32_t adst = sb + (uint32_t)(lr * 80 + ls * 32);
    const uint32_t bdst = sb + 10240u + (uint32_t)(lr * 80 + ls * 32);

    float acc[4][4][4];
    #pragma unroll
    for (int i = 0; i < 4; i++)
        #pragma unroll
        for (int j = 0; j < 4; j++)
            #pragma unroll
            for (int r = 0; r < 4; r++) acc[i][j][r] = 0.f;

    #pragma unroll
    for (int s = 0; s < 3; s++) {
        #pragma unroll
        for (int q = 0; q < 2; q++) {
            cp16(adst + s * S2 + q * 16, vsrc + s * 16 + q * 4);
            cp16(bdst + s * S2 + q * 16, wsrc + s * 16 + q * 4);
        }
        asm volatile("cp.async.commit_group;" ::: "memory");
    }

    asm volatile("cp.async.wait_group 2;" ::: "memory");
    __syncthreads();

    uint32_t af[2][4][4], bf[2][4][2];
    g2_frags((const uint32_t*)(sm), (const uint32_t*)(sm + 10240),
             0, mOff, nOff, g, tig, af[0], bf[0]);

    for (int c = 0; c < 32; c++) {
        const uint32_t* As = (const uint32_t*)(sm + (c & 3) * S2);
        const uint32_t* Bs = (const uint32_t*)(sm + (c & 3) * S2 + 10240);

        g2_frags(As, Bs, 8, mOff, nOff, g, tig, af[1], bf[1]);
        g_mmas4(acc, af[0], bf[0]);

        {
            const int s = c + 3;
            if (s < 32) {
                #pragma unroll
                for (int q = 0; q < 2; q++) {
                    cp16(adst + (s & 3) * S2 + q * 16, vsrc + s * 16 + q * 4);
                    cp16(bdst + (s & 3) * S2 + q * 16, wsrc + s * 16 + q * 4);
                }
            }
            asm volatile("cp.async.commit_group;" ::: "memory");
        }
        asm volatile("cp.async.wait_group 2;" ::: "memory");
        __syncthreads();

        if (c + 1 < 32) {
            const uint32_t* An = (const uint32_t*)(sm + ((c + 1) & 3) * S2);
            const uint32_t* Bn = (const uint32_t*)(sm + ((c + 1) & 3) * S2 + 10240);
            g2_frags(An, Bn, 0, mOff, nOff, g, tig, af[0], bf[0]);
        }
        g_mmas4(acc, af[1], bf[1]);
    }

    // epilogue: scale by Sinv[c]
    const float* Sn = Sinv + (size_t)n * CQ;
    #pragma unroll
    for (int i = 0; i < 4; i++) {
        const int row0 = d0 + mOff + 16 * i + g;
        #pragma unroll
        for (int j = 0; j < 4; j++) {
            const int colb = c0 + nOff + 8 * j + 2 * tig;
            const float si0 = Sn[colb];
            const float si1 = Sn[colb + 1];
            *(float2*)(Ob + (size_t)row0 * CQ + colb) =
                make_float2(acc[i][j][0] * si0, acc[i][j][1] * si1);
            *(float2*)(Ob + (size_t)(row0 + 8) * CQ + colb) =
                make_float2(acc[i][j][2] * si0, acc[i][j][3] * si1);
        }
    }
}

// ---------------------------------------------------------------------------
extern "C" void kernel_launch(void* const* d_in, const int* in_sizes, int n_in,
                              void* d_out, int out_size)
{
    const float* query  = (const float*)d_in[0];  // [64, 512, 512]
    const float* key    = (const float*)d_in[1];  // [64, 512, 1024]
    const float* value  = (const float*)d_in[2];  // [64, 512, 1024]
    const float* ratios = (const float*)d_in[3];  // [64]
    float* out = (float*)d_out;                   // [64, 512, 512]

    __half*   wh = nullptr;
    uint32_t *qh = nullptr, *kh = nullptr, *vh = nullptr;
    float    *sp = nullptr, *si = nullptr;
    cudaGetSymbolAddress((void**)&wh, g_wh);
    cudaGetSymbolAddress((void**)&qh, g_qh);
    cudaGetSymbolAddress((void**)&kh, g_kh);
    cudaGetSymbolAddress((void**)&vh, g_vh);
    cudaGetSymbolAddress((void**)&sp, g_Spart);
    cudaGetSymbolAddress((void**)&si, g_Sinv);

    cudaFuncSetAttribute(gemm_qk, cudaFuncAttributeMaxDynamicSharedMemorySize, SMEM1);
    cudaFuncSetAttribute(gemm_wv, cudaFuncAttributeMaxDynamicSharedMemorySize, SMEM2);

    // 0) conversions
    pairify<<<dim3(CQ / 512, DIM / 2, N_BATCH), 128>>>(query, qh, CQ, SCALE);
    pairify<<<dim3(TT / 512, DIM / 2, N_BATCH), 128>>>(key,   kh, TT, 1.0f);
    {
        const size_t n8 = (size_t)N_BATCH * DIM * TT / 8;
        vconv<<<(unsigned)(n8 / 256), 256>>>((const float4*)value, (uint4*)vh);
    }
    // 1) e = mask?exp((Q*SCALE)^T K):0  + partial sums
    {
        dim3 grid(TT / 128, CQ / 256, N_BATCH);  // (8, 2, 64)
        gemm_qk<<<grid, 256, SMEM1>>>(qh, kh, wh, sp, ratios);
    }
    // 2) Sinv = 1/rowsum
    sinv_kernel<<<(N_BATCH * CQ) / 256, 256>>>(sp, si);
    // 3) out = Sinv .* (V x e^T)
    {
        dim3 grid(CQ / 128, DIM / 128, N_BATCH);  // (4, 4, 64)
        gemm_wv<<<grid, 256, SMEM2>>>(vh, (const uint32_t*)wh, si, out);
    }
}